// round 2
// baseline (speedup 1.0000x reference)
#include <cuda_runtime.h>
#include <cstddef>

#define B_    4096
#define T_    128
#define NL_   256
#define NS_   64
#define NO_   32
#define V_    64

#define ROWS_ 32      // batch rows per CTA
#define NTH_  256     // threads per CTA (8 warps; warp w owns rows 4w..4w+3)
#define KB_   32      // K-chunk of W1 staged in smem per inner pass
#define XP_   260     // pitch (floats) of latent tiles; 260*4 = 1040 B (16B aligned, 260%32=4 ok for our patterns)
#define WSP_  33      // pitch (floats) of W1 stage tile; 33%32 == 1 -> conflict-free column reads

// Dynamic smem layout (floats):
//   xA   [32][260]      latent ping
//   xB   [32][260]      latent pong
//   ws   [256][33]      W1 K-chunk stage   (reused as W2 stage [32][260] in phase 2)
//   yb   [32][64]       scattered output rows
//   seq  [128] (int)    state sequence

__global__ void __launch_bounds__(NTH_, 1)
lalr_persistent_kernel(const float* __restrict__ latent0,
                       const float* __restrict__ W1,
                       const float* __restrict__ b1,
                       const float* __restrict__ W2,
                       const float* __restrict__ b2,
                       const int*   __restrict__ state_seq,
                       const int*   __restrict__ out_idx,
                       float*       __restrict__ out)
{
    extern __shared__ float sm[];
    float* xA  = sm;
    float* xB  = xA + ROWS_ * XP_;
    float* ws  = xB + ROWS_ * XP_;            // 256*33 floats
    float* yb  = ws + 256 * WSP_;             // 32*64 floats
    int*   seq = (int*)(yb + ROWS_ * V_);     // 128 ints

    const int tid  = threadIdx.x;
    const int w    = tid >> 5;
    const int lane = tid & 31;
    const int r0   = blockIdx.x * ROWS_;
    const int rw   = w * 4;                   // this warp's first local row

    if (tid < T_) seq[tid] = state_seq[tid];

    // Load initial latent tile (coalesced)
    for (int i = tid; i < ROWS_ * NL_; i += NTH_) {
        int r = i >> 8;          // / NL_
        int k = i & (NL_ - 1);
        xA[r * XP_ + k] = latent0[(size_t)(r0 + r) * NL_ + k];
    }
    __syncthreads();

    float* xcur = xA;
    float* xnew = xB;

    for (int t = 0; t < T_; ++t) {
        const int s = seq[t];
        const float* W1s = W1 + (size_t)s * (NL_ * NL_);

        // ---------------- Phase 1: x_new = tanh(x @ W1[s]^T + b1[s]) ----------------
        float acc[4][8];
        #pragma unroll
        for (int i = 0; i < 4; ++i)
            #pragma unroll
            for (int u = 0; u < 8; ++u) acc[i][u] = 0.0f;

        for (int kb = 0; kb < NL_; kb += KB_) {
            // Stage W1s[0:256, kb:kb+32] -> ws[j][kk]   (8192 floats, 8 float4/thread)
            #pragma unroll
            for (int l = 0; l < 8; ++l) {
                int idx4 = tid + l * NTH_;         // float4 index 0..2047
                int j    = idx4 >> 3;              // 8 float4 per 32-wide row
                int kk4  = (idx4 & 7) << 2;
                float4 v = *(const float4*)(W1s + (size_t)j * NL_ + kb + kk4);
                float* d = ws + j * WSP_ + kk4;    // pitch 33 not 16B-aligned -> scalar STS (conflict-free)
                d[0] = v.x; d[1] = v.y; d[2] = v.z; d[3] = v.w;
            }
            __syncthreads();

            const float* xr0 = xcur + (rw + 0) * XP_ + kb;
            const float* xr1 = xcur + (rw + 1) * XP_ + kb;
            const float* xr2 = xcur + (rw + 2) * XP_ + kb;
            const float* xr3 = xcur + (rw + 3) * XP_ + kb;

            #pragma unroll 4
            for (int kk = 0; kk < KB_; ++kk) {
                float x0 = xr0[kk];
                float x1 = xr1[kk];
                float x2 = xr2[kk];
                float x3 = xr3[kk];
                #pragma unroll
                for (int u = 0; u < 8; ++u) {
                    float wv = ws[(lane + 32 * u) * WSP_ + kk]; // lane stride 33 -> conflict-free
                    acc[0][u] = fmaf(x0, wv, acc[0][u]);
                    acc[1][u] = fmaf(x1, wv, acc[1][u]);
                    acc[2][u] = fmaf(x2, wv, acc[2][u]);
                    acc[3][u] = fmaf(x3, wv, acc[3][u]);
                }
            }
            __syncthreads();
        }

        // bias + tanh -> xnew
        #pragma unroll
        for (int u = 0; u < 8; ++u) {
            int j = lane + 32 * u;
            float bb = __ldg(b1 + s * NL_ + j);
            #pragma unroll
            for (int i = 0; i < 4; ++i)
                xnew[(rw + i) * XP_ + j] = tanhf(acc[i][u] + bb);
        }
        __syncthreads();

        // ---------------- Phase 2: probs = softmax(x_new @ W2[s]^T + b2[s]) --------
        // Stage W2[s] (32x256) into ws reused as [32][XP_]
        float* ws2 = ws;
        #pragma unroll
        for (int l = 0; l < 8; ++l) {
            int idx4 = tid + l * NTH_;             // 0..2047
            int o    = idx4 >> 6;                  // output neuron 0..31 (64 float4/row)
            int k4   = (idx4 & 63) << 2;
            float4 v = *(const float4*)(W2 + ((size_t)s * NO_ + o) * NL_ + k4);
            *(float4*)(ws2 + o * XP_ + k4) = v;    // row base 16B aligned
        }
        __syncthreads();

        float a2[4] = {0.f, 0.f, 0.f, 0.f};
        {
            const float4* wr = (const float4*)(ws2 + lane * XP_);
            const float4* x0 = (const float4*)(xnew + (rw + 0) * XP_);
            const float4* x1 = (const float4*)(xnew + (rw + 1) * XP_);
            const float4* x2 = (const float4*)(xnew + (rw + 2) * XP_);
            const float4* x3 = (const float4*)(xnew + (rw + 3) * XP_);
            #pragma unroll 8
            for (int k4 = 0; k4 < NL_ / 4; ++k4) {
                float4 wv = wr[k4];
                float4 v0 = x0[k4];
                a2[0] = fmaf(wv.x, v0.x, a2[0]); a2[0] = fmaf(wv.y, v0.y, a2[0]);
                a2[0] = fmaf(wv.z, v0.z, a2[0]); a2[0] = fmaf(wv.w, v0.w, a2[0]);
                float4 v1 = x1[k4];
                a2[1] = fmaf(wv.x, v1.x, a2[1]); a2[1] = fmaf(wv.y, v1.y, a2[1]);
                a2[1] = fmaf(wv.z, v1.z, a2[1]); a2[1] = fmaf(wv.w, v1.w, a2[1]);
                float4 v2 = x2[k4];
                a2[2] = fmaf(wv.x, v2.x, a2[2]); a2[2] = fmaf(wv.y, v2.y, a2[2]);
                a2[2] = fmaf(wv.z, v2.z, a2[2]); a2[2] = fmaf(wv.w, v2.w, a2[2]);
                float4 v3 = x3[k4];
                a2[3] = fmaf(wv.x, v3.x, a2[3]); a2[3] = fmaf(wv.y, v3.y, a2[3]);
                a2[3] = fmaf(wv.z, v3.z, a2[3]); a2[3] = fmaf(wv.w, v3.w, a2[3]);
            }
        }

        const float bb2  = __ldg(b2 + s * NO_ + lane);
        const int   idxv = __ldg(out_idx + s * NO_ + lane);
        // Last-wins scatter winner: highest lane among lanes sharing the same index
        const unsigned mm = __match_any_sync(0xffffffffu, idxv);
        const bool winner = (lane == (31 - __clz(mm)));

        #pragma unroll
        for (int i = 0; i < 4; ++i) {
            float v = a2[i] + bb2;
            // softmax across the 32 lanes (one row per i)
            float m = v;
            #pragma unroll
            for (int d = 16; d > 0; d >>= 1)
                m = fmaxf(m, __shfl_xor_sync(0xffffffffu, m, d));
            float e = expf(v - m);
            float ssum = e;
            #pragma unroll
            for (int d = 16; d > 0; d >>= 1)
                ssum += __shfl_xor_sync(0xffffffffu, ssum, d);
            float p = e / ssum;

            // zero the 64-slot row, scatter (last-wins), then coalesced store
            float* yrow = yb + (rw + i) * V_;
            yrow[lane]      = 0.0f;
            yrow[lane + 32] = 0.0f;
            __syncwarp();
            if (winner) yrow[idxv] = p;
            __syncwarp();
            float2 o2 = *(const float2*)(yrow + lane * 2);
            *(float2*)(out + ((size_t)(r0 + rw + i) * T_ + t) * V_ + lane * 2) = o2;
        }
        __syncthreads();   // protect ws/xnew before next step reuses them

        float* tmp = xcur; xcur = xnew; xnew = tmp;
    }
}

extern "C" void kernel_launch(void* const* d_in, const int* in_sizes, int n_in,
                              void* d_out, int out_size)
{
    const float* latent0   = (const float*)d_in[0];
    const float* W1        = (const float*)d_in[1];
    const float* b1        = (const float*)d_in[2];
    const float* W2        = (const float*)d_in[3];
    const float* b2        = (const float*)d_in[4];
    const int*   state_seq = (const int*)  d_in[5];
    const int*   out_idx   = (const int*)  d_in[6];
    float*       out       = (float*)      d_out;

    const int smem_bytes = (2 * ROWS_ * XP_ + 256 * WSP_ + ROWS_ * V_) * (int)sizeof(float)
                         + T_ * (int)sizeof(int);   // 109,056 B

    cudaFuncSetAttribute(lalr_persistent_kernel,
                         cudaFuncAttributeMaxDynamicSharedMemorySize, smem_bytes);

    lalr_persistent_kernel<<<B_ / ROWS_, NTH_, smem_bytes>>>(
        latent0, W1, b1, W2, b2, state_seq, out_idx, out);
}

// round 3
// speedup vs baseline: 1.2168x; 1.2168x over previous
#include <cuda_runtime.h>
#include <cstddef>

#define B_    4096
#define T_    128
#define NL_   256
#define NS_   64
#define NO_   32
#define V_    64

#define ROWS_ 32      // batch rows per CTA
#define NTH_  256     // 8 warps
#define KB_   32      // K per W1 chunk
#define NCH_  8       // chunks per step
#define XP_   260     // latent tile pitch (floats), 16B-aligned rows
#define WP_   34      // W1 stage pitch (floats): even (8B align) and 2-way max conflicts

typedef unsigned long long u64;

// Packed fp32x2 FMA (Blackwell): d.lo = a.lo*b.lo + c.lo ; d.hi likewise.
__device__ __forceinline__ u64 ffma2(u64 a, u64 b, u64 c) {
    u64 d;
    asm("fma.rn.f32x2 %0, %1, %2, %3;" : "=l"(d) : "l"(a), "l"(b), "l"(c));
    return d;
}

__device__ __forceinline__ void cp8(float* dst_smem, const float* src) {
    unsigned int d = (unsigned int)__cvta_generic_to_shared(dst_smem);
    asm volatile("cp.async.ca.shared.global [%0], [%1], 8;" :: "r"(d), "l"(src) : "memory");
}

// Stage one 256x32 chunk of W1[s] (verbatim, pitch WP_) via cp.async, 8B granules.
__device__ __forceinline__ void stage_chunk(const float* W1s, int kb, float* ws, int tid) {
    #pragma unroll
    for (int q = 0; q < 16; ++q) {
        int g  = tid + NTH_ * q;        // 0..4095
        int j  = g >> 4;                // 0..255
        int c2 = (g & 15) << 1;         // 0,2,..,30
        cp8(ws + j * WP_ + c2, W1s + (size_t)j * NL_ + kb + c2);
    }
    asm volatile("cp.async.commit_group;" ::: "memory");
}

// Dynamic smem (floats):
//   xA[32*260], xB[32*260]  latent ping/pong (row-major)
//   wsA[256*34], wsB[256*34] W1 chunk double buffer (wsB reused as W2 stage, pitch 260)
//   yb[32*64]               scatter rows
//   seq[128] (int)
__global__ void __launch_bounds__(NTH_, 1)
lalr_persistent_kernel(const float* __restrict__ latent0,
                       const float* __restrict__ W1,
                       const float* __restrict__ b1,
                       const float* __restrict__ W2,
                       const float* __restrict__ b2,
                       const int*   __restrict__ state_seq,
                       const int*   __restrict__ out_idx,
                       float*       __restrict__ out)
{
    extern __shared__ float sm[];
    float* xA  = sm;
    float* xB  = xA  + ROWS_ * XP_;
    float* wsA = xB  + ROWS_ * XP_;
    float* wsB = wsA + 256 * WP_;
    float* yb  = wsB + 256 * WP_;
    int*   seq = (int*)(yb + ROWS_ * V_);

    const int tid  = threadIdx.x;
    const int w    = tid >> 5;
    const int lane = tid & 31;
    const int r0   = blockIdx.x * ROWS_;

    const int rb1 = (w >> 1) * 8;      // phase-1 rows rb1..rb1+7
    const int jb  = (w & 1) * 128;     // phase-1 col half
    const int rw2 = w * 4;             // phase-2 rows rw2..rw2+3

    if (tid < T_) seq[tid] = state_seq[tid];

    for (int i = tid; i < ROWS_ * NL_; i += NTH_) {
        int r = i >> 8;
        int k = i & (NL_ - 1);
        xA[r * XP_ + k] = latent0[(size_t)(r0 + r) * NL_ + k];
    }

    // Prefetch chunk 0 of step 0 into wsA (state read straight from gmem).
    stage_chunk(W1 + (size_t)state_seq[0] * (NL_ * NL_), 0, wsA, tid);
    __syncthreads();

    float* xcur = xA;
    float* xnew = xB;

    for (int t = 0; t < T_; ++t) {
        const int s = seq[t];
        const float* W1s = W1 + (size_t)s * (NL_ * NL_);

        // ------------- Phase 1: x_new = tanh(x @ W1[s]^T + b1[s]) -------------
        u64 acc[8][4];
        #pragma unroll
        for (int i = 0; i < 8; ++i)
            #pragma unroll
            for (int v = 0; v < 4; ++v) acc[i][v] = 0ull;

        for (int c = 0; c < NCH_; ++c) {
            // Issue next chunk (c==NCH_-1 -> next step's chunk 0 into wsA).
            {
                const float* Wn; int kbn; float* bufn;
                int cn = c + 1;
                if (cn < NCH_) { Wn = W1s; kbn = cn * KB_; }
                else {
                    int sn = (t < T_ - 1) ? seq[t + 1] : s;
                    Wn = W1 + (size_t)sn * (NL_ * NL_); kbn = 0;
                }
                bufn = (cn & 1) ? wsB : wsA;
                stage_chunk(Wn, kbn, bufn, tid);
            }
            asm volatile("cp.async.wait_group 1;" ::: "memory");
            __syncthreads();

            const float* ws = (c & 1) ? wsB : wsA;
            const int kb = c * KB_;

            #pragma unroll
            for (int m4 = 0; m4 < KB_ / 4; ++m4) {          // 8 float4-steps
                ulonglong2 xq[8];
                #pragma unroll
                for (int i = 0; i < 8; ++i)
                    xq[i] = *(const ulonglong2*)(xcur + (rb1 + i) * XP_ + kb + 4 * m4);
                #pragma unroll
                for (int v = 0; v < 4; ++v) {
                    const float* wp = ws + (jb + lane + 32 * v) * WP_ + 4 * m4;
                    u64 wlo = *(const u64*)(wp);
                    u64 whi = *(const u64*)(wp + 2);
                    #pragma unroll
                    for (int i = 0; i < 8; ++i) {
                        acc[i][v] = ffma2(xq[i].x, wlo, acc[i][v]);
                        acc[i][v] = ffma2(xq[i].y, whi, acc[i][v]);
                    }
                }
            }
            __syncthreads();   // before next iteration overwrites buf[c&1]
        }

        // bias + tanh -> xnew  (conflict-free scalar stores)
        #pragma unroll
        for (int v = 0; v < 4; ++v) {
            int j = jb + lane + 32 * v;
            float bb = __ldg(b1 + s * NL_ + j);
            #pragma unroll
            for (int i = 0; i < 8; ++i) {
                float lo = __uint_as_float((unsigned)acc[i][v]);
                float hi = __uint_as_float((unsigned)(acc[i][v] >> 32));
                xnew[(rb1 + i) * XP_ + j] = tanhf(lo + hi + bb);
            }
        }
        __syncthreads();

        // ------------- Phase 2: probs = softmax(x_new @ W2[s]^T + b2[s]) -------
        // Stage W2[s] (32x256) into wsB (free: chunk 7 consumed; prefetch went to wsA).
        float* ws2 = wsB;
        #pragma unroll
        for (int l8 = 0; l8 < 8; ++l8) {
            int idx4 = tid + l8 * NTH_;
            int o    = idx4 >> 6;
            int k4   = (idx4 & 63) << 2;
            float4 vv = *(const float4*)(W2 + ((size_t)s * NO_ + o) * NL_ + k4);
            *(float4*)(ws2 + o * XP_ + k4) = vv;
        }
        __syncthreads();

        u64 a2[4] = {0ull, 0ull, 0ull, 0ull};
        {
            const ulonglong2* wr = (const ulonglong2*)(ws2 + lane * XP_);
            const ulonglong2* x0 = (const ulonglong2*)(xnew + (rw2 + 0) * XP_);
            const ulonglong2* x1 = (const ulonglong2*)(xnew + (rw2 + 1) * XP_);
            const ulonglong2* x2 = (const ulonglong2*)(xnew + (rw2 + 2) * XP_);
            const ulonglong2* x3 = (const ulonglong2*)(xnew + (rw2 + 3) * XP_);
            #pragma unroll 8
            for (int k4 = 0; k4 < NL_ / 4; ++k4) {
                ulonglong2 wv = wr[k4];
                ulonglong2 v0 = x0[k4];
                a2[0] = ffma2(wv.x, v0.x, a2[0]); a2[0] = ffma2(wv.y, v0.y, a2[0]);
                ulonglong2 v1 = x1[k4];
                a2[1] = ffma2(wv.x, v1.x, a2[1]); a2[1] = ffma2(wv.y, v1.y, a2[1]);
                ulonglong2 v2 = x2[k4];
                a2[2] = ffma2(wv.x, v2.x, a2[2]); a2[2] = ffma2(wv.y, v2.y, a2[2]);
                ulonglong2 v3 = x3[k4];
                a2[3] = ffma2(wv.x, v3.x, a2[3]); a2[3] = ffma2(wv.y, v3.y, a2[3]);
            }
        }

        const float bb2  = __ldg(b2 + s * NO_ + lane);
        const int   idxv = __ldg(out_idx + s * NO_ + lane);
        const unsigned mm = __match_any_sync(0xffffffffu, idxv);
        const bool winner = (lane == (31 - __clz(mm)));

        #pragma unroll
        for (int i = 0; i < 4; ++i) {
            float lo = __uint_as_float((unsigned)a2[i]);
            float hi = __uint_as_float((unsigned)(a2[i] >> 32));
            float v  = lo + hi + bb2;

            float m = v;
            #pragma unroll
            for (int d = 16; d > 0; d >>= 1)
                m = fmaxf(m, __shfl_xor_sync(0xffffffffu, m, d));
            float e = expf(v - m);
            float ssum = e;
            #pragma unroll
            for (int d = 16; d > 0; d >>= 1)
                ssum += __shfl_xor_sync(0xffffffffu, ssum, d);
            float p = e / ssum;

            float* yrow = yb + (rw2 + i) * V_;
            yrow[lane]      = 0.0f;
            yrow[lane + 32] = 0.0f;
            __syncwarp();
            if (winner) yrow[idxv] = p;
            __syncwarp();
            float2 o2 = *(const float2*)(yrow + lane * 2);
            *(float2*)(out + ((size_t)(r0 + rw2 + i) * T_ + t) * V_ + lane * 2) = o2;
        }
        __syncthreads();   // phase2 done with ws2/xnew before next step restages

        float* tmp = xcur; xcur = xnew; xnew = tmp;
    }
}

extern "C" void kernel_launch(void* const* d_in, const int* in_sizes, int n_in,
                              void* d_out, int out_size)
{
    const float* latent0   = (const float*)d_in[0];
    const float* W1        = (const float*)d_in[1];
    const float* b1        = (const float*)d_in[2];
    const float* W2        = (const float*)d_in[3];
    const float* b2        = (const float*)d_in[4];
    const int*   state_seq = (const int*)  d_in[5];
    const int*   out_idx   = (const int*)  d_in[6];
    float*       out       = (float*)      d_out;

    const int smem_bytes = (2 * ROWS_ * XP_ + 2 * 256 * WP_ + ROWS_ * V_) * (int)sizeof(float)
                         + T_ * (int)sizeof(int);   // 144,896 B

    cudaFuncSetAttribute(lalr_persistent_kernel,
                         cudaFuncAttributeMaxDynamicSharedMemorySize, smem_bytes);

    lalr_persistent_kernel<<<B_ / ROWS_, NTH_, smem_bytes>>>(
        latent0, W1, b1, W2, b2, state_seq, out_idx, out);
}